// round 11
// baseline (speedup 1.0000x reference)
#include <cuda_runtime.h>
#include <cstdint>

#define DEVI __device__ __forceinline__

// Problem constants
static constexpr int B_TOT  = 16384;
static constexpr int F_DIM  = 50;
static constexpr int E_DIM  = 64;
static constexpr int D_DIM  = 128;
static constexpr int FE     = F_DIM * E_DIM;      // 3200 floats per batch

// Kernel config: 3 CTAs/SM, 256 threads (8 warps), 2 batches per CTA-iteration
static constexpr int NTHREADS = 256;
static constexpr int GRID     = 456;              // 3 CTAs per SM on GB300
static constexpr int BPI      = 2;
static constexpr int NGI      = B_TOT / BPI;      // 8192 groups

// fp16 tile: [f2 rows 0..31][e 64] stride 72 (rows 25..31 zero pad)
static constexpr int F2_REAL   = 25;
static constexpr int X16_STR   = 72;
static constexpr int X16_BATCH = 32 * X16_STR;               // 2304 u32
static constexpr int X16_BUF   = BPI * X16_BATCH;            // 4608 u32

// A-frag table: [mq(4)][s(4)][mi(2)][lane(32)][reg(4)] u32 (f16x2, frag order)
static constexpr int AFRAG_U32 = 4 * 4 * 2 * 32 * 4;         // 4096

// SMEM map (u32) — no fp32 staging tier anymore
static constexpr int X16_OFF   = AFRAG_U32;                  // 4096
static constexpr int SMEM_U32  = X16_OFF + 2 * X16_BUF;      // 13312
static constexpr int SMEM_BYTES = SMEM_U32 * 4;              // 53248 B -> 3 CTAs/SM

// Pairs per group for the owned convert: b(2) x f2(25) x seg(16)
static constexpr int NPAIRS = BPI * F2_REAL * 16;            // 800

// ---------------------------------------------------------------------------
DEVI uint32_t pack_h2(float lo, float hi) {
    uint32_t r;
    asm("cvt.rn.f16x2.f32 %0, %1, %2;" : "=r"(r) : "f"(hi), "f"(lo));
    return r;
}
DEVI void mma16n8k16(float& c0, float& c1, float& c2, float& c3,
                     uint32_t a0, uint32_t a1, uint32_t a2, uint32_t a3,
                     uint32_t b0, uint32_t b1) {
    asm volatile(
        "mma.sync.aligned.m16n8k16.row.col.f32.f16.f16.f32 "
        "{%0,%1,%2,%3}, {%4,%5,%6,%7}, {%8,%9}, {%0,%1,%2,%3};"
        : "+f"(c0), "+f"(c1), "+f"(c2), "+f"(c3)
        : "r"(a0), "r"(a1), "r"(a2), "r"(a3), "r"(b0), "r"(b1));
}

// Owned convert, direct from gmem: thread loads its pairs (2 x LDG.128),
// packs fp16x2, stores one STS.128 per pair. No barrier needed around gmem.
DEVI void convertg(uint32_t* __restrict__ x16dst, const float* __restrict__ gb, int tid) {
#pragma unroll 1
    for (int p = tid; p < NPAIRS; p += NTHREADS) {
        int b   = p / 400;
        int r   = p - b * 400;
        int f2  = r >> 4;
        int seg = r & 15;
        const float* p0 = gb + b * FE + (2 * f2) * E_DIM + seg * 4;
        float4 lo = *reinterpret_cast<const float4*>(p0);
        float4 hi = *reinterpret_cast<const float4*>(p0 + E_DIM);
        uint4 q;
        q.x = pack_h2(lo.x, hi.x);
        q.y = pack_h2(lo.y, hi.y);
        q.z = pack_h2(lo.z, hi.z);
        q.w = pack_h2(lo.w, hi.w);
        *reinterpret_cast<uint4*>(x16dst + b * X16_BATCH + f2 * X16_STR + seg * 4) = q;
    }
}

// ---------------------------------------------------------------------------
__global__ void __launch_bounds__(NTHREADS, 3)
InnerProduct_65429531787441_kernel(const float* __restrict__ X,
                                   const float* __restrict__ Th,
                                   float* __restrict__ out) {
    extern __shared__ uint32_t smu[];
    uint32_t* afr = smu;                             // A-frag table (f16x2)
    uint32_t* x16 = smu + X16_OFF;                   // fp16 B tile (2 buffers)

    const int tid  = threadIdx.x;
    const int lane = tid & 31;
    const int w    = tid >> 5;
    const int b_l  = w >> 2;        // batch slot 0..1
    const int mq   = w & 3;         // d quarter
    const int lg   = lane >> 2;     // 0..7
    const int lq   = lane & 3;      // 0..3

    const int gi0 = blockIdx.x;

    // Build A-frag table (Theta fp16 pairs, m16n8k16 frag order, zero-pad f>=50)
    for (int i = tid; i < AFRAG_U32; i += NTHREADS) {
        int j   = i & 3;
        int ln  = (i >> 2) & 31;
        int mi  = (i >> 7) & 1;
        int s   = (i >> 8) & 3;
        int mq_ = i >> 10;
        int row = mq_ * 32 + mi * 16 + (j & 1) * 8 + (ln >> 2);
        int k0  = 16 * s + 2 * (ln & 3) + (j >> 1) * 8;
        float v0 = (k0     < F_DIM) ? Th[row * F_DIM + k0]     : 0.f;
        float v1 = (k0 + 1 < F_DIM) ? Th[row * F_DIM + k0 + 1] : 0.f;
        afr[i] = pack_h2(v0, v1);
    }
    // Zero pad f2-rows 25..31 in all 4 (buf, batch) slots (stable forever)
    for (int i = tid; i < 2 * BPI * (32 - F2_REAL) * X16_STR; i += NTHREADS) {
        int slot = i / ((32 - F2_REAL) * X16_STR);
        int r    = i % ((32 - F2_REAL) * X16_STR);
        x16[slot * X16_BATCH + F2_REAL * X16_STR + r] = 0u;
    }

    // Prologue: convert group gi0 into x16[0], publish everything
    convertg(x16, X + (size_t)gi0 * (BPI * FE), tid);
    __syncthreads();

    const uint4* afr4 = reinterpret_cast<const uint4*>(afr);

    int it = 0;
    for (int gi = gi0; gi < NGI; gi += GRID, ++it) {
        const int buf = it & 1;

        // MMA on current group from x16[buf] (published by last barrier)
        const uint32_t* xb = x16 + buf * X16_BUF + b_l * X16_BATCH;

        float acc[2][8][4];
#pragma unroll
        for (int mi = 0; mi < 2; mi++)
#pragma unroll
            for (int ni = 0; ni < 8; ni++)
#pragma unroll
                for (int j = 0; j < 4; j++) acc[mi][ni][j] = 0.f;

#pragma unroll
        for (int s = 0; s < 4; s++) {
            uint4 A0 = afr4[((mq * 4 + s) * 2 + 0) * 32 + lane];
            uint4 A1 = afr4[((mq * 4 + s) * 2 + 1) * 32 + lane];
            const int f2a = 8 * s + lq;
            // <=2 live B regs per ni step: keeps us under the 85-reg cap
#pragma unroll
            for (int ni = 0; ni < 8; ni++) {
                const int e = ni * 8 + lg;
                uint32_t b0 = xb[f2a * X16_STR + e];
                uint32_t b1 = xb[(f2a + 4) * X16_STR + e];
                mma16n8k16(acc[0][ni][0], acc[0][ni][1], acc[0][ni][2], acc[0][ni][3],
                           A0.x, A0.y, A0.z, A0.w, b0, b1);
                mma16n8k16(acc[1][ni][0], acc[1][ni][1], acc[1][ni][2], acc[1][ni][3],
                           A1.x, A1.y, A1.z, A1.w, b0, b1);
            }
        }

        // Epilogue: sum of squares over this warp's full e-range, shfl, store
        float* orow = out + (size_t)(gi * BPI + b_l) * D_DIM;
#pragma unroll
        for (int mi = 0; mi < 2; mi++) {
            float a = 0.f, b = 0.f;
#pragma unroll
            for (int ni = 0; ni < 8; ni++) {
                a = fmaf(acc[mi][ni][0], acc[mi][ni][0], a);
                a = fmaf(acc[mi][ni][1], acc[mi][ni][1], a);
                b = fmaf(acc[mi][ni][2], acc[mi][ni][2], b);
                b = fmaf(acc[mi][ni][3], acc[mi][ni][3], b);
            }
            a += __shfl_xor_sync(0xffffffffu, a, 1);
            a += __shfl_xor_sync(0xffffffffu, a, 2);
            b += __shfl_xor_sync(0xffffffffu, b, 1);
            b += __shfl_xor_sync(0xffffffffu, b, 2);
            if (lq == 0) {
                const int d = mq * 32 + mi * 16 + lg;
                orow[d]     = a;
                orow[d + 8] = b;
            }
        }

        // Convert NEXT group directly from gmem into the other x16 buffer.
        // LDGs carry no deps on the MMA above -> ptxas can hoist them early;
        // with 6 warps/SMSP the DRAM latency is covered by other warps' HMMA.
        if (gi + GRID < NGI)
            convertg(x16 + (buf ^ 1) * X16_BUF,
                     X + (size_t)(gi + GRID) * (BPI * FE), tid);

        __syncthreads();   // publish x16[buf^1]; close all reads of x16[buf]
    }
}

extern "C" void kernel_launch(void* const* d_in, const int* in_sizes, int n_in,
                              void* d_out, int out_size) {
    (void)in_sizes; (void)n_in; (void)out_size;
    const float* X  = (const float*)d_in[0];
    const float* Th = (const float*)d_in[1];
    float* out = (float*)d_out;
    cudaFuncSetAttribute(InnerProduct_65429531787441_kernel,
                         cudaFuncAttributeMaxDynamicSharedMemorySize, SMEM_BYTES);
    InnerProduct_65429531787441_kernel<<<GRID, NTHREADS, SMEM_BYTES>>>(X, Th, out);
}